// round 6
// baseline (speedup 1.0000x reference)
#include <cuda_runtime.h>
#include <stdint.h>

// Problem constants (fixed: v is [32, 2, 512, 512] fp32)
#define NB 32
#define HH 512
#define WW 512
#define HW (HH * WW)          // 262144 = 2^18
#define TOTAL (NB * HW)       // 8388608
#define NO_STEPS 16
#define SCALE 0x1p-16f        // 1 / 2^16

// Batch grouping for L2 residency.
#define G_IMGS 16
#define N_GROUPS (NB / G_IMGS)
#define G_PIX (G_IMGS * HW)

// Tiled-step geometry: 32x32 output tile, halo 16 -> 64x64 smem tile (32 KB).
#define TOUT 32
#define HALO 16
#define TIN 64
#define TILES_PER_IMG ((WW / TOUT) * (HH / TOUT))   // 256

// Last step whose *input* field is safe for halo-16 tiling:
// tap offset (px) <= 2^(k-1) * |v| / 256 ; step 11 uses wf_10 -> 4*|v| px.
// (The fallback path keeps correctness exact even when this is exceeded.)
#define LAST_TILED_STEP 11

// Ping-pong scratch: warp field interleaved [n][y][x] -> float2(ch0, ch1).
__device__ float2 g_bufA[TOTAL];
__device__ float2 g_bufB[TOTAL];

// ---------------------------------------------------------------------------
// Bilinear sample, border clamp, align_corners=False, interleaved float2 plane.
// ---------------------------------------------------------------------------
__device__ __forceinline__ float2 sample_plane(const float2* __restrict__ plane,
                                               float sx, float sy) {
    float ix = fminf(fmaxf(((sx + 1.0f) * (float)WW - 1.0f) * 0.5f, 0.0f), (float)(WW - 1));
    float iy = fminf(fmaxf(((sy + 1.0f) * (float)HH - 1.0f) * 0.5f, 0.0f), (float)(HH - 1));
    float fx0 = floorf(ix);
    float fy0 = floorf(iy);
    int x0 = (int)fx0, y0 = (int)fy0;
    int x1 = min(x0 + 1, WW - 1);
    int y1 = min(y0 + 1, HH - 1);
    float wx = ix - fx0, wy = iy - fy0;
    float2 a = __ldg(plane + y0 * WW + x0);
    float2 b = __ldg(plane + y0 * WW + x1);
    float2 c = __ldg(plane + y1 * WW + x0);
    float2 d = __ldg(plane + y1 * WW + x1);
    float owx = 1.0f - wx, owy = 1.0f - wy;
    float2 top, bot, r;
    top.x = a.x * owx + b.x * wx;  top.y = a.y * owx + b.y * wx;
    bot.x = c.x * owx + d.x * wx;  bot.y = c.y * owx + d.y * wx;
    r.x = top.x * owy + bot.x * wy;
    r.y = top.y * owy + bot.y * wy;
    return r;
}

// Same math, but taps served from the smem tile when in range, else exact
// global fallback. Bit-identical to sample_plane (same tap values/ops).
__device__ __forceinline__ float2 sample_tiled(const float2* __restrict__ tile,
                                               const float2* __restrict__ plane,
                                               int tx0, int ty0,
                                               float sx, float sy) {
    float ix = fminf(fmaxf(((sx + 1.0f) * (float)WW - 1.0f) * 0.5f, 0.0f), (float)(WW - 1));
    float iy = fminf(fmaxf(((sy + 1.0f) * (float)HH - 1.0f) * 0.5f, 0.0f), (float)(HH - 1));
    float fx0 = floorf(ix);
    float fy0 = floorf(iy);
    int x0 = (int)fx0, y0 = (int)fy0;
    int x1 = min(x0 + 1, WW - 1);
    int y1 = min(y0 + 1, HH - 1);
    float wx = ix - fx0, wy = iy - fy0;
    float owx = 1.0f - wx, owy = 1.0f - wy;
    int lx0 = x0 - tx0, ly0 = y0 - ty0;
    int lx1 = x1 - tx0, ly1 = y1 - ty0;
    float2 a, b, c, d;
    if (lx0 >= 0 && lx1 < TIN && ly0 >= 0 && ly1 < TIN) {
        a = tile[ly0 * TIN + lx0];
        b = tile[ly0 * TIN + lx1];
        c = tile[ly1 * TIN + lx0];
        d = tile[ly1 * TIN + lx1];
    } else {
        a = __ldg(plane + y0 * WW + x0);
        b = __ldg(plane + y0 * WW + x1);
        c = __ldg(plane + y1 * WW + x0);
        d = __ldg(plane + y1 * WW + x1);
    }
    float2 top, bot, r;
    top.x = a.x * owx + b.x * wx;  top.y = a.y * owx + b.y * wx;
    bot.x = c.x * owx + d.x * wx;  bot.y = c.y * owx + d.y * wx;
    r.x = top.x * owy + bot.x * wy;
    r.y = top.y * owy + bot.y * wy;
    return r;
}

// Bilinear over NCHW v planes with 2^-16 scale folded into every tap.
__device__ __forceinline__ float2 sample_v(const float* __restrict__ p0,
                                           const float* __restrict__ p1,
                                           float sx, float sy) {
    float ix = fminf(fmaxf(((sx + 1.0f) * (float)WW - 1.0f) * 0.5f, 0.0f), (float)(WW - 1));
    float iy = fminf(fmaxf(((sy + 1.0f) * (float)HH - 1.0f) * 0.5f, 0.0f), (float)(HH - 1));
    float fx0 = floorf(ix);
    float fy0 = floorf(iy);
    int x0 = (int)fx0, y0 = (int)fy0;
    int x1 = min(x0 + 1, WW - 1);
    int y1 = min(y0 + 1, HH - 1);
    float wx = ix - fx0, wy = iy - fy0;
    int i00 = y0 * WW + x0, i01 = y0 * WW + x1, i10 = y1 * WW + x0, i11 = y1 * WW + x1;
    float owx = 1.0f - wx, owy = 1.0f - wy;
    float2 r;
    {
        float a = __ldg(p0 + i00) * SCALE, b = __ldg(p0 + i01) * SCALE;
        float c = __ldg(p0 + i10) * SCALE, d = __ldg(p0 + i11) * SCALE;
        r.x = (a * owx + b * wx) * owy + (c * owx + d * wx) * wy;
    }
    {
        float a = __ldg(p1 + i00) * SCALE, b = __ldg(p1 + i01) * SCALE;
        float c = __ldg(p1 + i10) * SCALE, d = __ldg(p1 + i11) * SCALE;
        r.y = (a * owx + b * wx) * owy + (c * owx + d * wx) * wy;
    }
    return r;
}

// ---------------------------------------------------------------------------
// Step 1 fused with init: wf0 = v*2^-16 ; out = wf0 + sample(wf0, id+wf0)
// ---------------------------------------------------------------------------
__global__ __launch_bounds__(256)
void svf_first_g(const float* __restrict__ v, const float2* __restrict__ ig,
                 float2* __restrict__ dst, int n0) {
    int t = blockIdx.x * blockDim.x + threadIdx.x;
    int p = t << 1;
    if (p >= G_PIX) return;
    int local = p & (HW - 1);
    int img = n0 + (p >> 18);
    const float* p0 = v + (size_t)img * 2 * HW;
    const float* p1 = p0 + HW;
    float2 c0 = *reinterpret_cast<const float2*>(p0 + local);
    float2 c1 = *reinterpret_cast<const float2*>(p1 + local);
    float wfx0 = c0.x * SCALE, wfx1 = c0.y * SCALE;
    float wfy0 = c1.x * SCALE, wfy1 = c1.y * SCALE;
    float4 g = __ldg(reinterpret_cast<const float4*>(ig + local));
    float2 sm0 = sample_v(p0, p1, g.x + wfx0, g.y + wfy0);
    float2 sm1 = sample_v(p0, p1, g.z + wfx1, g.w + wfy1);
    float4 o;
    o.x = wfx0 + sm0.x;  o.y = wfy0 + sm0.y;
    o.z = wfx1 + sm1.x;  o.w = wfy1 + sm1.y;
    *reinterpret_cast<float4*>(dst + ((size_t)img << 18) + local) = o;
}

// ---------------------------------------------------------------------------
// Tiled middle step (steps 2..LAST_TILED_STEP): taps from smem tile.
// Block = 256 threads; output 32x32 px; smem tile 64x64 float2 (32 KB).
// ---------------------------------------------------------------------------
__global__ __launch_bounds__(256)
void svf_step_tile(const float2* __restrict__ src, const float2* __restrict__ ig,
                   float2* __restrict__ dst, int n0) {
    __shared__ float2 tile[TIN * TIN];
    int tid = threadIdx.x;
    int b = blockIdx.x;
    if (b >= TILES_PER_IMG * G_IMGS) return;
    int img = n0 + (b >> 8);                 // 256 tiles per image
    int tl = b & 255;
    int tx0 = (tl & 15) * TOUT - HALO;       // tile origin (may be <0)
    int ty0 = (tl >> 4) * TOUT - HALO;
    const float2* plane = src + ((size_t)img << 18);
    float2* dplane = dst + ((size_t)img << 18);

    // Cooperative tile load: rows coalesced (64 float2 = 512B per row).
    for (int i = tid; i < TIN * TIN; i += 256) {
        int r = i >> 6, c = i & 63;
        int gr = min(max(ty0 + r, 0), HH - 1);
        int gc = min(max(tx0 + c, 0), WW - 1);
        tile[i] = __ldg(plane + gr * WW + gc);
    }
    __syncthreads();

    // Each thread: 2 pixel-pairs (rows lr and lr+16 of the 32x32 output tile).
    int lr = tid >> 4;            // 0..15
    int lc = (tid & 15) * 2;      // 0,2,..,30
    for (int rep = 0; rep < 2; ++rep) {
        int oy = lr + rep * 16;                 // 0..31
        int gy = ty0 + HALO + oy;
        int gx = tx0 + HALO + lc;
        int local = gy * WW + gx;
        // center values from smem (tile interior)
        float4 s = *reinterpret_cast<const float4*>(tile + (oy + HALO) * TIN + (lc + HALO));
        float4 g = __ldg(reinterpret_cast<const float4*>(ig + local));
        float2 sm0 = sample_tiled(tile, plane, tx0, ty0, g.x + s.x, g.y + s.y);
        float2 sm1 = sample_tiled(tile, plane, tx0, ty0, g.z + s.z, g.w + s.w);
        float4 o;
        o.x = s.x + sm0.x;  o.y = s.y + sm0.y;
        o.z = s.z + sm1.x;  o.w = s.w + sm1.y;
        *reinterpret_cast<float4*>(dplane + local) = o;
    }
}

// ---------------------------------------------------------------------------
// Global middle step (late steps with large displacement).
// ---------------------------------------------------------------------------
__global__ __launch_bounds__(256)
void svf_step_g(const float2* __restrict__ src, const float2* __restrict__ ig,
                float2* __restrict__ dst, int n0) {
    int t = blockIdx.x * blockDim.x + threadIdx.x;
    int p = t << 1;
    if (p >= G_PIX) return;
    int local = p & (HW - 1);
    int img = n0 + (p >> 18);
    const float2* plane = src + ((size_t)img << 18);
    float4 s = *reinterpret_cast<const float4*>(plane + local);
    float4 g = __ldg(reinterpret_cast<const float4*>(ig + local));
    float2 sm0 = sample_plane(plane, g.x + s.x, g.y + s.y);
    float2 sm1 = sample_plane(plane, g.z + s.z, g.w + s.w);
    float4 o;
    o.x = s.x + sm0.x;  o.y = s.y + sm0.y;
    o.z = s.z + sm1.x;  o.w = s.w + sm1.y;
    *reinterpret_cast<float4*>(dst + ((size_t)img << 18) + local) = o;
}

// ---------------------------------------------------------------------------
// Last step fused with epilogue: writes transformation & warp_field (NCHW).
// d_out layout: [transformation (N,2,H,W) | warp_field (N,2,H,W)]
// ---------------------------------------------------------------------------
__global__ __launch_bounds__(256)
void svf_last_g(const float2* __restrict__ src, const float2* __restrict__ ig,
                float* __restrict__ out, int n0) {
    int t = blockIdx.x * blockDim.x + threadIdx.x;
    int p = t << 1;
    if (p >= G_PIX) return;
    int local = p & (HW - 1);
    int img = n0 + (p >> 18);
    const float2* plane = src + ((size_t)img << 18);
    float4 s = *reinterpret_cast<const float4*>(plane + local);
    float4 g = __ldg(reinterpret_cast<const float4*>(ig + local));
    float2 sm0 = sample_plane(plane, g.x + s.x, g.y + s.y);
    float2 sm1 = sample_plane(plane, g.z + s.z, g.w + s.w);
    float wfx0 = s.x + sm0.x, wfy0 = s.y + sm0.y;
    float wfx1 = s.z + sm1.x, wfy1 = s.w + sm1.y;
    size_t base = ((size_t)img * 2) * HW + local;
    const size_t half = (size_t)NB * 2 * HW;
    float2 tx;  tx.x = wfx0 + g.x;  tx.y = wfx1 + g.z;
    float2 ty;  ty.x = wfy0 + g.y;  ty.y = wfy1 + g.w;
    float2 wxo; wxo.x = wfx0;       wxo.y = wfx1;
    float2 wyo; wyo.x = wfy0;       wyo.y = wfy1;
    *reinterpret_cast<float2*>(out + base)              = tx;
    *reinterpret_cast<float2*>(out + base + HW)         = ty;
    *reinterpret_cast<float2*>(out + half + base)       = wxo;
    *reinterpret_cast<float2*>(out + half + base + HW)  = wyo;
}

extern "C" void kernel_launch(void* const* d_in, const int* in_sizes, int n_in,
                              void* d_out, int out_size) {
    const float*  v  = (const float*)d_in[0];
    const float2* ig = (const float2*)d_in[1];
    float* out = (float*)d_out;

    float2* bufA = nullptr;
    float2* bufB = nullptr;
    cudaGetSymbolAddress((void**)&bufA, g_bufA);
    cudaGetSymbolAddress((void**)&bufB, g_bufB);

    const int threads = 256;
    const int blocksG = (G_PIX / 2 + threads - 1) / threads;   // 2 px/thread
    const int blocksT = TILES_PER_IMG * G_IMGS;                // tiled kernel

    for (int g = 0; g < N_GROUPS; ++g) {
        int n0 = g * G_IMGS;
        svf_first_g<<<blocksG, threads>>>(v, ig, bufA, n0);
        float2* cur = bufA;
        float2* nxt = bufB;
        for (int k = 2; k <= NO_STEPS - 1; ++k) {
            if (k <= LAST_TILED_STEP)
                svf_step_tile<<<blocksT, threads>>>(cur, ig, nxt, n0);
            else
                svf_step_g<<<blocksG, threads>>>(cur, ig, nxt, n0);
            float2* tswap = cur; cur = nxt; nxt = tswap;
        }
        svf_last_g<<<blocksG, threads>>>(cur, ig, out, n0);
    }
}

// round 8
// speedup vs baseline: 1.0901x; 1.0901x over previous
#include <cuda_runtime.h>
#include <stdint.h>

// Problem constants (fixed: v is [32, 2, 512, 512] fp32)
#define NB 32
#define HH 512
#define WW 512
#define HW (HH * WW)          // 262144 = 2^18
#define TOTAL (NB * HW)       // 8388608
#define NO_STEPS 16
#define SCALE 0x1p-16f        // 1 / 2^16

// Batch grouping for L2 residency.
#define G_IMGS 16
#define N_GROUPS (NB / G_IMGS)
#define G_PIX (G_IMGS * HW)

// Ping-pong scratch: warp field interleaved [n][y][x] -> float2(ch0, ch1).
__device__ float2 g_bufA[TOTAL];
__device__ float2 g_bufB[TOTAL];

// ---------------------------------------------------------------------------
// Bilinear sample, border clamp, align_corners=False, interleaved float2 plane.
// ---------------------------------------------------------------------------
__device__ __forceinline__ float2 sample_plane(const float2* __restrict__ plane,
                                               float sx, float sy) {
    float ix = fminf(fmaxf(((sx + 1.0f) * (float)WW - 1.0f) * 0.5f, 0.0f), (float)(WW - 1));
    float iy = fminf(fmaxf(((sy + 1.0f) * (float)HH - 1.0f) * 0.5f, 0.0f), (float)(HH - 1));
    float fx0 = floorf(ix);
    float fy0 = floorf(iy);
    int x0 = (int)fx0, y0 = (int)fy0;
    int x1 = min(x0 + 1, WW - 1);
    int y1 = min(y0 + 1, HH - 1);
    float wx = ix - fx0, wy = iy - fy0;
    float2 a = __ldg(plane + y0 * WW + x0);
    float2 b = __ldg(plane + y0 * WW + x1);
    float2 c = __ldg(plane + y1 * WW + x0);
    float2 d = __ldg(plane + y1 * WW + x1);
    float owx = 1.0f - wx, owy = 1.0f - wy;
    float2 top, bot, r;
    top.x = a.x * owx + b.x * wx;  top.y = a.y * owx + b.y * wx;
    bot.x = c.x * owx + d.x * wx;  bot.y = c.y * owx + d.y * wx;
    r.x = top.x * owy + bot.x * wy;
    r.y = top.y * owy + bot.y * wy;
    return r;
}

// Bilinear over NCHW v planes with 2^-16 scale folded into every tap.
__device__ __forceinline__ float2 sample_v(const float* __restrict__ p0,
                                           const float* __restrict__ p1,
                                           float sx, float sy) {
    float ix = fminf(fmaxf(((sx + 1.0f) * (float)WW - 1.0f) * 0.5f, 0.0f), (float)(WW - 1));
    float iy = fminf(fmaxf(((sy + 1.0f) * (float)HH - 1.0f) * 0.5f, 0.0f), (float)(HH - 1));
    float fx0 = floorf(ix);
    float fy0 = floorf(iy);
    int x0 = (int)fx0, y0 = (int)fy0;
    int x1 = min(x0 + 1, WW - 1);
    int y1 = min(y0 + 1, HH - 1);
    float wx = ix - fx0, wy = iy - fy0;
    int i00 = y0 * WW + x0, i01 = y0 * WW + x1, i10 = y1 * WW + x0, i11 = y1 * WW + x1;
    float owx = 1.0f - wx, owy = 1.0f - wy;
    float2 r;
    {
        float a = __ldg(p0 + i00) * SCALE, b = __ldg(p0 + i01) * SCALE;
        float c = __ldg(p0 + i10) * SCALE, d = __ldg(p0 + i11) * SCALE;
        r.x = (a * owx + b * wx) * owy + (c * owx + d * wx) * wy;
    }
    {
        float a = __ldg(p1 + i00) * SCALE, b = __ldg(p1 + i01) * SCALE;
        float c = __ldg(p1 + i10) * SCALE, d = __ldg(p1 + i11) * SCALE;
        r.y = (a * owx + b * wx) * owy + (c * owx + d * wx) * wy;
    }
    return r;
}

// Process one pixel-pair (two adjacent pixels) of a middle step.
__device__ __forceinline__ float4 step_pair(const float2* __restrict__ plane,
                                            float4 s, float4 g) {
    float2 sm0 = sample_plane(plane, g.x + s.x, g.y + s.y);
    float2 sm1 = sample_plane(plane, g.z + s.z, g.w + s.w);
    float4 o;
    o.x = s.x + sm0.x;  o.y = s.y + sm0.y;
    o.z = s.z + sm1.x;  o.w = s.w + sm1.y;
    return o;
}

// ---------------------------------------------------------------------------
// Step 1 fused with init: wf0 = v*2^-16 ; out = wf0 + sample(wf0, id+wf0)
// 4 px per thread.
// ---------------------------------------------------------------------------
__global__ __launch_bounds__(256)
void svf_first_g(const float* __restrict__ v, const float2* __restrict__ ig,
                 float2* __restrict__ dst, int n0) {
    int t = blockIdx.x * blockDim.x + threadIdx.x;
    int p = t << 2;                                  // 4-pixel start
    if (p >= G_PIX) return;
    int local = p & (HW - 1);
    int img = n0 + (p >> 18);
    const float* p0 = v + (size_t)img * 2 * HW;
    const float* p1 = p0 + HW;
    float4 c0 = *reinterpret_cast<const float4*>(p0 + local);  // ch0 x 4 px
    float4 c1 = *reinterpret_cast<const float4*>(p1 + local);  // ch1 x 4 px
    float4 ga = __ldg(reinterpret_cast<const float4*>(ig + local));
    float4 gb = __ldg(reinterpret_cast<const float4*>(ig + local + 2));
    float wfx0 = c0.x * SCALE, wfx1 = c0.y * SCALE, wfx2 = c0.z * SCALE, wfx3 = c0.w * SCALE;
    float wfy0 = c1.x * SCALE, wfy1 = c1.y * SCALE, wfy2 = c1.z * SCALE, wfy3 = c1.w * SCALE;
    float2 sm0 = sample_v(p0, p1, ga.x + wfx0, ga.y + wfy0);
    float2 sm1 = sample_v(p0, p1, ga.z + wfx1, ga.w + wfy1);
    float2 sm2 = sample_v(p0, p1, gb.x + wfx2, gb.y + wfy2);
    float2 sm3 = sample_v(p0, p1, gb.z + wfx3, gb.w + wfy3);
    float4 oa, ob;
    oa.x = wfx0 + sm0.x;  oa.y = wfy0 + sm0.y;
    oa.z = wfx1 + sm1.x;  oa.w = wfy1 + sm1.y;
    ob.x = wfx2 + sm2.x;  ob.y = wfy2 + sm2.y;
    ob.z = wfx3 + sm3.x;  ob.w = wfy3 + sm3.y;
    float2* d = dst + ((size_t)img << 18) + local;
    *reinterpret_cast<float4*>(d)     = oa;
    *reinterpret_cast<float4*>(d + 2) = ob;
}

// ---------------------------------------------------------------------------
// Middle step: wf' = wf + sample(wf, id + wf). 4 px per thread.
// ---------------------------------------------------------------------------
__global__ __launch_bounds__(256)
void svf_step_g(const float2* __restrict__ src, const float2* __restrict__ ig,
                float2* __restrict__ dst, int n0) {
    int t = blockIdx.x * blockDim.x + threadIdx.x;
    int p = t << 2;
    if (p >= G_PIX) return;
    int local = p & (HW - 1);
    int img = n0 + (p >> 18);
    const float2* plane = src + ((size_t)img << 18);
    float4 sa = *reinterpret_cast<const float4*>(plane + local);
    float4 sb = *reinterpret_cast<const float4*>(plane + local + 2);
    float4 ga = __ldg(reinterpret_cast<const float4*>(ig + local));
    float4 gb = __ldg(reinterpret_cast<const float4*>(ig + local + 2));
    float4 oa = step_pair(plane, sa, ga);
    float4 ob = step_pair(plane, sb, gb);
    float2* d = dst + ((size_t)img << 18) + local;
    *reinterpret_cast<float4*>(d)     = oa;
    *reinterpret_cast<float4*>(d + 2) = ob;
}

// ---------------------------------------------------------------------------
// Last step fused with epilogue: writes transformation & warp_field (NCHW).
// d_out layout: [transformation (N,2,H,W) | warp_field (N,2,H,W)]
// 4 px per thread -> float4 stores on every output stream.
// ---------------------------------------------------------------------------
__global__ __launch_bounds__(256)
void svf_last_g(const float2* __restrict__ src, const float2* __restrict__ ig,
                float* __restrict__ out, int n0) {
    int t = blockIdx.x * blockDim.x + threadIdx.x;
    int p = t << 2;
    if (p >= G_PIX) return;
    int local = p & (HW - 1);
    int img = n0 + (p >> 18);
    const float2* plane = src + ((size_t)img << 18);
    float4 sa = *reinterpret_cast<const float4*>(plane + local);
    float4 sb = *reinterpret_cast<const float4*>(plane + local + 2);
    float4 ga = __ldg(reinterpret_cast<const float4*>(ig + local));
    float4 gb = __ldg(reinterpret_cast<const float4*>(ig + local + 2));
    float2 sm0 = sample_plane(plane, ga.x + sa.x, ga.y + sa.y);
    float2 sm1 = sample_plane(plane, ga.z + sa.z, ga.w + sa.w);
    float2 sm2 = sample_plane(plane, gb.x + sb.x, gb.y + sb.y);
    float2 sm3 = sample_plane(plane, gb.z + sb.z, gb.w + sb.w);
    float wfx0 = sa.x + sm0.x, wfy0 = sa.y + sm0.y;
    float wfx1 = sa.z + sm1.x, wfy1 = sa.w + sm1.y;
    float wfx2 = sb.x + sm2.x, wfy2 = sb.y + sm2.y;
    float wfx3 = sb.z + sm3.x, wfy3 = sb.w + sm3.y;
    size_t base = ((size_t)img * 2) * HW + local;   // ch0 plane offset (NCHW)
    const size_t half = (size_t)NB * 2 * HW;        // start of warp_field output
    float4 tx;  tx.x = wfx0 + ga.x;  tx.y = wfx1 + ga.z;  tx.z = wfx2 + gb.x;  tx.w = wfx3 + gb.z;
    float4 ty;  ty.x = wfy0 + ga.y;  ty.y = wfy1 + ga.w;  ty.z = wfy2 + gb.y;  ty.w = wfy3 + gb.w;
    float4 wx;  wx.x = wfx0;  wx.y = wfx1;  wx.z = wfx2;  wx.w = wfx3;
    float4 wy;  wy.x = wfy0;  wy.y = wfy1;  wy.z = wfy2;  wy.w = wfy3;
    *reinterpret_cast<float4*>(out + base)             = tx;  // transformation ch0
    *reinterpret_cast<float4*>(out + base + HW)        = ty;  // transformation ch1
    *reinterpret_cast<float4*>(out + half + base)      = wx;  // warp_field ch0
    *reinterpret_cast<float4*>(out + half + base + HW) = wy;  // warp_field ch1
}

extern "C" void kernel_launch(void* const* d_in, const int* in_sizes, int n_in,
                              void* d_out, int out_size) {
    const float*  v  = (const float*)d_in[0];
    const float2* ig = (const float2*)d_in[1];   // [1,H,W,2] contiguous
    float* out = (float*)d_out;

    float2* bufA = nullptr;
    float2* bufB = nullptr;
    cudaGetSymbolAddress((void**)&bufA, g_bufA);
    cudaGetSymbolAddress((void**)&bufB, g_bufB);

    const int threads = 256;
    const int blocks = (G_PIX / 4 + threads - 1) / threads;   // 4 px per thread

    for (int g = 0; g < N_GROUPS; ++g) {
        int n0 = g * G_IMGS;
        svf_first_g<<<blocks, threads>>>(v, ig, bufA, n0);
        float2* cur = bufA;
        float2* nxt = bufB;
        for (int k = 2; k <= NO_STEPS - 1; ++k) {
            svf_step_g<<<blocks, threads>>>(cur, ig, nxt, n0);
            float2* tswap = cur; cur = nxt; nxt = tswap;
        }
        svf_last_g<<<blocks, threads>>>(cur, ig, out, n0);
    }
}

// round 9
// speedup vs baseline: 1.3903x; 1.2753x over previous
#include <cuda_runtime.h>
#include <stdint.h>

// Problem constants (fixed: v is [32, 2, 512, 512] fp32)
#define NB 32
#define HH 512
#define WW 512
#define HW (HH * WW)          // 262144 = 2^18
#define TOTAL (NB * HW)       // 8388608
#define NO_STEPS 16
#define SCALE 0x1p-16f        // 1 / 2^16

// Batch grouping: 8 images -> 2 x 16 MiB ping-pong working set (L2-resident).
#define G_IMGS 8
#define N_GROUPS (NB / G_IMGS)
#define IMG_STRIDE (G_IMGS / 2)     // second image handled by same thread

// Ping-pong scratch: warp field interleaved [n][y][x] -> float2(ch0, ch1).
__device__ float2 g_bufA[TOTAL];
__device__ float2 g_bufB[TOTAL];

// ---------------------------------------------------------------------------
// Bilinear sample, border clamp, align_corners=False, interleaved float2 plane.
// Coordinate math is kept bit-identical to the reference:
//   ix = clamp(((sx + 1) * W - 1) * 0.5, 0, W-1)   (power-of-2 muls exact)
// ---------------------------------------------------------------------------
__device__ __forceinline__ float2 sample_plane(const float2* __restrict__ plane,
                                               float sx, float sy) {
    float ix = fminf(fmaxf(((sx + 1.0f) * (float)WW - 1.0f) * 0.5f, 0.0f), (float)(WW - 1));
    float iy = fminf(fmaxf(((sy + 1.0f) * (float)HH - 1.0f) * 0.5f, 0.0f), (float)(HH - 1));
    float fx0 = floorf(ix);
    float fy0 = floorf(iy);
    int x0 = (int)fx0, y0 = (int)fy0;
    int x1 = min(x0 + 1, WW - 1);
    int y1 = min(y0 + 1, HH - 1);
    float wx = ix - fx0, wy = iy - fy0;
    float2 a = __ldg(plane + y0 * WW + x0);
    float2 b = __ldg(plane + y0 * WW + x1);
    float2 c = __ldg(plane + y1 * WW + x0);
    float2 d = __ldg(plane + y1 * WW + x1);
    float owx = 1.0f - wx, owy = 1.0f - wy;
    float2 top, bot, r;
    top.x = a.x * owx + b.x * wx;  top.y = a.y * owx + b.y * wx;
    bot.x = c.x * owx + d.x * wx;  bot.y = c.y * owx + d.y * wx;
    r.x = top.x * owy + bot.x * wy;
    r.y = top.y * owy + bot.y * wy;
    return r;
}

// Bilinear over NCHW v planes with 2^-16 scale folded into every tap.
__device__ __forceinline__ float2 sample_v(const float* __restrict__ p0,
                                           const float* __restrict__ p1,
                                           float sx, float sy) {
    float ix = fminf(fmaxf(((sx + 1.0f) * (float)WW - 1.0f) * 0.5f, 0.0f), (float)(WW - 1));
    float iy = fminf(fmaxf(((sy + 1.0f) * (float)HH - 1.0f) * 0.5f, 0.0f), (float)(HH - 1));
    float fx0 = floorf(ix);
    float fy0 = floorf(iy);
    int x0 = (int)fx0, y0 = (int)fy0;
    int x1 = min(x0 + 1, WW - 1);
    int y1 = min(y0 + 1, HH - 1);
    float wx = ix - fx0, wy = iy - fy0;
    int i00 = y0 * WW + x0, i01 = y0 * WW + x1, i10 = y1 * WW + x0, i11 = y1 * WW + x1;
    float owx = 1.0f - wx, owy = 1.0f - wy;
    float2 r;
    {
        float a = __ldg(p0 + i00) * SCALE, b = __ldg(p0 + i01) * SCALE;
        float c = __ldg(p0 + i10) * SCALE, d = __ldg(p0 + i11) * SCALE;
        r.x = (a * owx + b * wx) * owy + (c * owx + d * wx) * wy;
    }
    {
        float a = __ldg(p1 + i00) * SCALE, b = __ldg(p1 + i01) * SCALE;
        float c = __ldg(p1 + i10) * SCALE, d = __ldg(p1 + i11) * SCALE;
        r.y = (a * owx + b * wx) * owy + (c * owx + d * wx) * wy;
    }
    return r;
}

// One middle-step pixel-pair (two adjacent pixels of one image).
__device__ __forceinline__ float4 step_pair(const float2* __restrict__ plane,
                                            float4 s, float4 g) {
    float2 sm0 = sample_plane(plane, g.x + s.x, g.y + s.y);
    float2 sm1 = sample_plane(plane, g.z + s.z, g.w + s.w);
    float4 o;
    o.x = s.x + sm0.x;  o.y = s.y + sm0.y;
    o.z = s.z + sm1.x;  o.w = s.w + sm1.y;
    return o;
}

// ---------------------------------------------------------------------------
// Step 1 fused with init: wf0 = v*2^-16 ; out = wf0 + sample(wf0, id+wf0)
// Each thread: same pixel-pair of TWO images (q and q+IMG_STRIDE); ig shared.
// ---------------------------------------------------------------------------
__global__ __launch_bounds__(256)
void svf_first_g(const float* __restrict__ v, const float2* __restrict__ ig,
                 float2* __restrict__ dst, int n0) {
    int t = blockIdx.x * blockDim.x + threadIdx.x;
    int lp = t & (HW / 2 - 1);
    int q  = t >> 17;
    int local = lp << 1;
    int imgA = n0 + q;
    int imgB = imgA + IMG_STRIDE;
    const float* a0 = v + (size_t)imgA * 2 * HW;
    const float* a1 = a0 + HW;
    const float* b0 = v + (size_t)imgB * 2 * HW;
    const float* b1 = b0 + HW;
    float4 g = __ldg(reinterpret_cast<const float4*>(ig + local));
    // image A
    float2 cA0 = *reinterpret_cast<const float2*>(a0 + local);
    float2 cA1 = *reinterpret_cast<const float2*>(a1 + local);
    // image B
    float2 cB0 = *reinterpret_cast<const float2*>(b0 + local);
    float2 cB1 = *reinterpret_cast<const float2*>(b1 + local);
    float Ax0 = cA0.x * SCALE, Ax1 = cA0.y * SCALE, Ay0 = cA1.x * SCALE, Ay1 = cA1.y * SCALE;
    float Bx0 = cB0.x * SCALE, Bx1 = cB0.y * SCALE, By0 = cB1.x * SCALE, By1 = cB1.y * SCALE;
    float2 smA0 = sample_v(a0, a1, g.x + Ax0, g.y + Ay0);
    float2 smA1 = sample_v(a0, a1, g.z + Ax1, g.w + Ay1);
    float2 smB0 = sample_v(b0, b1, g.x + Bx0, g.y + By0);
    float2 smB1 = sample_v(b0, b1, g.z + Bx1, g.w + By1);
    float4 oA, oB;
    oA.x = Ax0 + smA0.x;  oA.y = Ay0 + smA0.y;
    oA.z = Ax1 + smA1.x;  oA.w = Ay1 + smA1.y;
    oB.x = Bx0 + smB0.x;  oB.y = By0 + smB0.y;
    oB.z = Bx1 + smB1.x;  oB.w = By1 + smB1.y;
    *reinterpret_cast<float4*>(dst + ((size_t)imgA << 18) + local) = oA;
    *reinterpret_cast<float4*>(dst + ((size_t)imgB << 18) + local) = oB;
}

// ---------------------------------------------------------------------------
// Middle step: wf' = wf + sample(wf, id + wf). 2 images x 2 px per thread.
// ---------------------------------------------------------------------------
__global__ __launch_bounds__(256)
void svf_step_g(const float2* __restrict__ src, const float2* __restrict__ ig,
                float2* __restrict__ dst, int n0) {
    int t = blockIdx.x * blockDim.x + threadIdx.x;
    int lp = t & (HW / 2 - 1);
    int q  = t >> 17;
    int local = lp << 1;
    int imgA = n0 + q;
    int imgB = imgA + IMG_STRIDE;
    const float2* plA = src + ((size_t)imgA << 18);
    const float2* plB = src + ((size_t)imgB << 18);
    float4 sA = *reinterpret_cast<const float4*>(plA + local);
    float4 sB = *reinterpret_cast<const float4*>(plB + local);
    float4 g  = __ldg(reinterpret_cast<const float4*>(ig + local));
    float4 oA = step_pair(plA, sA, g);
    float4 oB = step_pair(plB, sB, g);
    *reinterpret_cast<float4*>(dst + ((size_t)imgA << 18) + local) = oA;
    *reinterpret_cast<float4*>(dst + ((size_t)imgB << 18) + local) = oB;
}

// ---------------------------------------------------------------------------
// Last step fused with epilogue: writes transformation & warp_field (NCHW).
// d_out layout: [transformation (N,2,H,W) | warp_field (N,2,H,W)]
// ---------------------------------------------------------------------------
__device__ __forceinline__ void last_store(float* __restrict__ out, int img,
                                           int local, float4 s, float4 g,
                                           const float2* __restrict__ plane) {
    float2 sm0 = sample_plane(plane, g.x + s.x, g.y + s.y);
    float2 sm1 = sample_plane(plane, g.z + s.z, g.w + s.w);
    float wfx0 = s.x + sm0.x, wfy0 = s.y + sm0.y;
    float wfx1 = s.z + sm1.x, wfy1 = s.w + sm1.y;
    size_t base = ((size_t)img * 2) * HW + local;   // ch0 plane offset (NCHW)
    const size_t half = (size_t)NB * 2 * HW;        // start of warp_field output
    float2 tx;  tx.x = wfx0 + g.x;  tx.y = wfx1 + g.z;
    float2 ty;  ty.x = wfy0 + g.y;  ty.y = wfy1 + g.w;
    float2 wxo; wxo.x = wfx0;       wxo.y = wfx1;
    float2 wyo; wyo.x = wfy0;       wyo.y = wfy1;
    *reinterpret_cast<float2*>(out + base)              = tx;
    *reinterpret_cast<float2*>(out + base + HW)         = ty;
    *reinterpret_cast<float2*>(out + half + base)       = wxo;
    *reinterpret_cast<float2*>(out + half + base + HW)  = wyo;
}

__global__ __launch_bounds__(256)
void svf_last_g(const float2* __restrict__ src, const float2* __restrict__ ig,
                float* __restrict__ out, int n0) {
    int t = blockIdx.x * blockDim.x + threadIdx.x;
    int lp = t & (HW / 2 - 1);
    int q  = t >> 17;
    int local = lp << 1;
    int imgA = n0 + q;
    int imgB = imgA + IMG_STRIDE;
    const float2* plA = src + ((size_t)imgA << 18);
    const float2* plB = src + ((size_t)imgB << 18);
    float4 sA = *reinterpret_cast<const float4*>(plA + local);
    float4 sB = *reinterpret_cast<const float4*>(plB + local);
    float4 g  = __ldg(reinterpret_cast<const float4*>(ig + local));
    last_store(out, imgA, local, sA, g, plA);
    last_store(out, imgB, local, sB, g, plB);
}

extern "C" void kernel_launch(void* const* d_in, const int* in_sizes, int n_in,
                              void* d_out, int out_size) {
    const float*  v  = (const float*)d_in[0];
    const float2* ig = (const float2*)d_in[1];   // [1,H,W,2] contiguous
    float* out = (float*)d_out;

    float2* bufA = nullptr;
    float2* bufB = nullptr;
    cudaGetSymbolAddress((void**)&bufA, g_bufA);
    cudaGetSymbolAddress((void**)&bufB, g_bufB);

    const int threads = 256;
    // (G_IMGS/2) image-pairs * HW/2 pixel-pairs per step kernel
    const int blocks = (IMG_STRIDE * (HW / 2)) / threads;   // 2048

    for (int g = 0; g < N_GROUPS; ++g) {
        int n0 = g * G_IMGS;
        svf_first_g<<<blocks, threads>>>(v, ig, bufA, n0);
        float2* cur = bufA;
        float2* nxt = bufB;
        for (int k = 2; k <= NO_STEPS - 1; ++k) {
            svf_step_g<<<blocks, threads>>>(cur, ig, nxt, n0);
            float2* tswap = cur; cur = nxt; nxt = tswap;
        }
        svf_last_g<<<blocks, threads>>>(cur, ig, out, n0);
    }
}

// round 10
// speedup vs baseline: 1.7062x; 1.2272x over previous
#include <cuda_runtime.h>
#include <stdint.h>

// Problem constants (fixed: v is [32, 2, 512, 512] fp32)
#define NB 32
#define HH 512
#define WW 512
#define HW (HH * WW)          // 262144 = 2^18
#define HALF (HW / 2)         // 131072 = 2^17
#define TOTAL (NB * HW)       // 8388608
#define NO_STEPS 16
#define SCALE 0x1p-16f        // 1 / 2^16

// Ping-pong scratch: warp field interleaved [n][y][x] -> float2(ch0, ch1).
__device__ float2 g_bufA[TOTAL];
__device__ float2 g_bufB[TOTAL];

// ---------------------------------------------------------------------------
// Bilinear sample, border clamp, align_corners=False, interleaved float2 plane.
// Coordinate math bit-identical to reference; power-of-2 muls exact.
// ---------------------------------------------------------------------------
__device__ __forceinline__ float2 sample_plane(const float2* __restrict__ plane,
                                               float sx, float sy) {
    float ix = fminf(fmaxf(((sx + 1.0f) * (float)WW - 1.0f) * 0.5f, 0.0f), (float)(WW - 1));
    float iy = fminf(fmaxf(((sy + 1.0f) * (float)HH - 1.0f) * 0.5f, 0.0f), (float)(HH - 1));
    float fx0 = floorf(ix);
    float fy0 = floorf(iy);
    int x0 = (int)fx0, y0 = (int)fy0;
    int x1 = min(x0 + 1, WW - 1);
    int y1 = min(y0 + 1, HH - 1);
    float wx = ix - fx0, wy = iy - fy0;
    float2 a = __ldg(plane + y0 * WW + x0);
    float2 b = __ldg(plane + y0 * WW + x1);
    float2 c = __ldg(plane + y1 * WW + x0);
    float2 d = __ldg(plane + y1 * WW + x1);
    float owx = 1.0f - wx, owy = 1.0f - wy;
    float2 top, bot, r;
    top.x = a.x * owx + b.x * wx;  top.y = a.y * owx + b.y * wx;
    bot.x = c.x * owx + d.x * wx;  bot.y = c.y * owx + d.y * wx;
    r.x = top.x * owy + bot.x * wy;
    r.y = top.y * owy + bot.y * wy;
    return r;
}

// Bilinear over NCHW v planes with 2^-16 scale folded into every tap.
__device__ __forceinline__ float2 sample_v(const float* __restrict__ p0,
                                           const float* __restrict__ p1,
                                           float sx, float sy) {
    float ix = fminf(fmaxf(((sx + 1.0f) * (float)WW - 1.0f) * 0.5f, 0.0f), (float)(WW - 1));
    float iy = fminf(fmaxf(((sy + 1.0f) * (float)HH - 1.0f) * 0.5f, 0.0f), (float)(HH - 1));
    float fx0 = floorf(ix);
    float fy0 = floorf(iy);
    int x0 = (int)fx0, y0 = (int)fy0;
    int x1 = min(x0 + 1, WW - 1);
    int y1 = min(y0 + 1, HH - 1);
    float wx = ix - fx0, wy = iy - fy0;
    int i00 = y0 * WW + x0, i01 = y0 * WW + x1, i10 = y1 * WW + x0, i11 = y1 * WW + x1;
    float owx = 1.0f - wx, owy = 1.0f - wy;
    float2 r;
    {
        float a = __ldg(p0 + i00) * SCALE, b = __ldg(p0 + i01) * SCALE;
        float c = __ldg(p0 + i10) * SCALE, d = __ldg(p0 + i11) * SCALE;
        r.x = (a * owx + b * wx) * owy + (c * owx + d * wx) * wy;
    }
    {
        float a = __ldg(p1 + i00) * SCALE, b = __ldg(p1 + i01) * SCALE;
        float c = __ldg(p1 + i10) * SCALE, d = __ldg(p1 + i11) * SCALE;
        r.y = (a * owx + b * wx) * owy + (c * owx + d * wx) * wy;
    }
    return r;
}

// ---------------------------------------------------------------------------
// Step 1 fused with init: wf0 = v*2^-16 ; out = wf0 + sample(wf0, id+wf0)
// Each thread: pixels lp and lp+HALF of one image (contiguous warp accesses,
// 2-way ILP). All 32 images per launch.
// ---------------------------------------------------------------------------
__global__ __launch_bounds__(256)
void svf_first(const float* __restrict__ v, const float2* __restrict__ ig,
               float2* __restrict__ dst) {
    int t = blockIdx.x * blockDim.x + threadIdx.x;   // TOTAL/2 threads
    int lp  = t & (HALF - 1);
    int img = t >> 17;
    int l0 = lp, l1 = lp + HALF;
    const float* p0 = v + (size_t)img * 2 * HW;      // ch0 plane
    const float* p1 = p0 + HW;                       // ch1 plane
    float s0x = __ldg(p0 + l0) * SCALE, s0y = __ldg(p1 + l0) * SCALE;
    float s1x = __ldg(p0 + l1) * SCALE, s1y = __ldg(p1 + l1) * SCALE;
    float2 g0 = __ldg(ig + l0);
    float2 g1 = __ldg(ig + l1);
    float2 sm0 = sample_v(p0, p1, g0.x + s0x, g0.y + s0y);
    float2 sm1 = sample_v(p0, p1, g1.x + s1x, g1.y + s1y);
    float2* d = dst + ((size_t)img << 18);
    float2 o0; o0.x = s0x + sm0.x; o0.y = s0y + sm0.y;
    float2 o1; o1.x = s1x + sm1.x; o1.y = s1y + sm1.y;
    d[l0] = o0;
    d[l1] = o1;
}

// ---------------------------------------------------------------------------
// Middle step: wf' = wf + sample(wf, id + wf). 2 far-apart px per thread.
// ---------------------------------------------------------------------------
__global__ __launch_bounds__(256)
void svf_step(const float2* __restrict__ src, const float2* __restrict__ ig,
              float2* __restrict__ dst) {
    int t = blockIdx.x * blockDim.x + threadIdx.x;
    int lp  = t & (HALF - 1);
    int img = t >> 17;
    int l0 = lp, l1 = lp + HALF;
    const float2* plane = src + ((size_t)img << 18);
    float2 s0 = plane[l0];
    float2 s1 = plane[l1];
    float2 g0 = __ldg(ig + l0);
    float2 g1 = __ldg(ig + l1);
    float2 sm0 = sample_plane(plane, g0.x + s0.x, g0.y + s0.y);
    float2 sm1 = sample_plane(plane, g1.x + s1.x, g1.y + s1.y);
    float2* d = dst + ((size_t)img << 18);
    float2 o0; o0.x = s0.x + sm0.x; o0.y = s0.y + sm0.y;
    float2 o1; o1.x = s1.x + sm1.x; o1.y = s1.y + sm1.y;
    d[l0] = o0;
    d[l1] = o1;
}

// ---------------------------------------------------------------------------
// Last step fused with epilogue: writes transformation & warp_field (NCHW).
// d_out layout: [transformation (N,2,H,W) | warp_field (N,2,H,W)]
// ---------------------------------------------------------------------------
__global__ __launch_bounds__(256)
void svf_last(const float2* __restrict__ src, const float2* __restrict__ ig,
              float* __restrict__ out) {
    int t = blockIdx.x * blockDim.x + threadIdx.x;
    int lp  = t & (HALF - 1);
    int img = t >> 17;
    const float2* plane = src + ((size_t)img << 18);
    const size_t half = (size_t)NB * 2 * HW;
    size_t ch0 = ((size_t)img * 2) * HW;
    #pragma unroll
    for (int rep = 0; rep < 2; ++rep) {
        int l = lp + rep * HALF;
        float2 s = plane[l];
        float2 g = __ldg(ig + l);
        float2 sm = sample_plane(plane, g.x + s.x, g.y + s.y);
        float wfx = s.x + sm.x, wfy = s.y + sm.y;
        size_t base = ch0 + l;
        out[base]             = wfx + g.x;   // transformation ch0
        out[base + HW]        = wfy + g.y;   // transformation ch1
        out[half + base]      = wfx;         // warp_field ch0
        out[half + base + HW] = wfy;         // warp_field ch1
    }
}

extern "C" void kernel_launch(void* const* d_in, const int* in_sizes, int n_in,
                              void* d_out, int out_size) {
    const float*  v  = (const float*)d_in[0];
    const float2* ig = (const float2*)d_in[1];   // [1,H,W,2] contiguous
    float* out = (float*)d_out;

    float2* bufA = nullptr;
    float2* bufB = nullptr;
    cudaGetSymbolAddress((void**)&bufA, g_bufA);
    cudaGetSymbolAddress((void**)&bufB, g_bufB);

    const int threads = 256;
    const int blocks = (TOTAL / 2) / threads;    // 16384

    // step 1: v -> bufA
    svf_first<<<blocks, threads>>>(v, ig, bufA);

    // steps 2..15: ping-pong
    float2* cur = bufA;
    float2* nxt = bufB;
    for (int k = 2; k <= NO_STEPS - 1; ++k) {
        svf_step<<<blocks, threads>>>(cur, ig, nxt);
        float2* tswap = cur; cur = nxt; nxt = tswap;
    }

    // step 16: cur -> d_out
    svf_last<<<blocks, threads>>>(cur, ig, out);
}